// round 8
// baseline (speedup 1.0000x reference)
#include <cuda_runtime.h>
#include <cuda_fp16.h>
#include <cstdint>

// GroupConv2D via warp-level fp16 HMMA (mma.sync.m16n8k16, f32 accum).
// Block = (g, b, 8-row band): 448 px = 28 m-tiles; 7 warps x 4 m-tiles.
// B operand (weights) ldmatrix amortized over 4 m-tiles; weights staged once
// per 8 output rows. Dynamic smem (55.5 KB).
// d_in[0]=inputs [32,56,56,256] f32, d_in[1]=kernel [3,3,32,256] f32,
// d_in[2]=bias [256] f32, d_out = [32,56,56,256] f32.

namespace {
constexpr int B = 32, H = 56, W = 56, C = 256, CG = 32;
constexpr int ROWS = 8;                      // output rows per block
constexpr int IN_ROWS = ROWS + 2;            // 10 staged input rows
constexpr int NCOL = 58;                     // cols: ww = -1..56
constexpr int IN_SM_BYTES = IN_ROWS * NCOL * 64;   // 37120
constexpr int KTOT = 288;                    // 3*3*32
constexpr int W_SM_BYTES = KTOT * 64;        // 18432
constexpr int SMEM_TOTAL = IN_SM_BYTES + W_SM_BYTES; // 55552
constexpr int NSTEP = KTOT / 16;             // 18
constexpr int THREADS = 224;                 // 7 warps
constexpr int MT = 4;                        // m-tiles per warp
}

__device__ __forceinline__ uint32_t smem_u32(const void* p) {
    return (uint32_t)__cvta_generic_to_shared(p);
}

__device__ __forceinline__ uint4 cvt8_f32_to_f16(float4 v0, float4 v1) {
    __half2 h0 = __floats2half2_rn(v0.x, v0.y);
    __half2 h1 = __floats2half2_rn(v0.z, v0.w);
    __half2 h2 = __floats2half2_rn(v1.x, v1.y);
    __half2 h3 = __floats2half2_rn(v1.z, v1.w);
    uint4 r;
    r.x = *reinterpret_cast<uint32_t*>(&h0);
    r.y = *reinterpret_cast<uint32_t*>(&h1);
    r.z = *reinterpret_cast<uint32_t*>(&h2);
    r.w = *reinterpret_cast<uint32_t*>(&h3);
    return r;
}

__global__ __launch_bounds__(THREADS, 2)
void groupconv_hmma(const float* __restrict__ in,
                    const float* __restrict__ wgt,
                    const float* __restrict__ bias,
                    float* __restrict__ out)
{
    extern __shared__ __align__(16) unsigned char smem_dyn[];
    unsigned char* in_sm = smem_dyn;
    unsigned char* w_sm  = smem_dyn + IN_SM_BYTES;

    const int bid = blockIdx.x;
    const int g  = bid & 7;
    const int hq = (bid >> 3) % (H / ROWS);   // 0..6
    const int b  = bid / (8 * (H / ROWS));
    const int h0 = hq * ROWS;

    const int tid  = threadIdx.x;
    const int lane = tid & 31;
    const int warp = tid >> 5;                // 0..6

    // ---- Stage input: rows h0-1..h0+8, cols -1..56, this group's 32 ch ----
    for (int cid = tid; cid < IN_ROWS * NCOL * 4; cid += THREADS) {
        const int r   = cid / (NCOL * 4);
        const int rem = cid - r * (NCOL * 4);
        const int col = rem >> 2;
        const int j8  = rem & 3;
        const int hh = h0 - 1 + r;
        const int ww = col - 1;
        uint4 st = make_uint4(0u, 0u, 0u, 0u);
        if (hh >= 0 && hh < H && ww >= 0 && ww < W) {
            const float4* src = reinterpret_cast<const float4*>(
                &in[(((long)b * H + hh) * W + ww) * C + g * CG + j8 * 8]);
            st = cvt8_f32_to_f16(src[0], src[1]);
        }
        const int gran = j8 ^ ((col >> 1) & 3);
        *reinterpret_cast<uint4*>(&in_sm[(r * NCOL + col) * 64 + gran * 16]) = st;
    }

    // ---- Stage weights: B[k=288][n=32] fp16, gran = nt ^ ((k>>1)&3) ----
    for (int cid = tid; cid < KTOT * 4; cid += THREADS) {
        const int k  = cid >> 2;
        const int nt = cid & 3;
        const float4* src = reinterpret_cast<const float4*>(
            &wgt[(long)k * C + g * CG + nt * 8]);
        uint4 st = cvt8_f32_to_f16(src[0], src[1]);
        const int gran = nt ^ ((k >> 1) & 3);
        *reinterpret_cast<uint4*>(&w_sm[k * 64 + gran * 16]) = st;
    }
    __syncthreads();

    const uint32_t in_base = smem_u32(in_sm);
    const uint32_t w_base  = smem_u32(w_sm);

    // ---- A lane geometry: 4 m-tiles per warp, 16 linear pixels each ----
    const int q = lane >> 4;                  // 0/1 = k-half select
    int colpart[MT][3];
    int csel[MT][3];
#pragma unroll
    for (int t = 0; t < MT; ++t) {
        const int px = (warp * MT + t) * 16 + (lane & 15);
        const int hr = px / W;
        const int wc = px - hr * W;
#pragma unroll
        for (int kw = 0; kw < 3; ++kw) {
            const int c = wc + kw;            // 0..57
            colpart[t][kw] = (hr * NCOL + c) * 64;
            csel[t][kw]    = (c >> 1) & 3;
        }
    }

    // ---- B lane geometry: ldmatrix.x4.trans, 2 n-tiles per op ----
    const int li = lane & 15;
    const int kx = (li >> 1) & 3;
    uint32_t boff[2];
#pragma unroll
    for (int ntp = 0; ntp < 2; ++ntp)
        boff[ntp] = (uint32_t)(li * 64 + (((ntp * 2 + q) ^ kx) * 16));

    float acc[MT][4][4];
#pragma unroll
    for (int t = 0; t < MT; ++t)
#pragma unroll
        for (int nt = 0; nt < 4; ++nt)
#pragma unroll
            for (int i = 0; i < 4; ++i) acc[t][nt][i] = 0.f;

    // ---- Main loop: s = (kh*3 + kw)*2 + cih ----
#pragma unroll
    for (int s = 0; s < NSTEP; ++s) {
        const int kh  = s / 6;
        const int kw  = (s / 2) % 3;
        const int cih = s & 1;
        const int j   = cih * 2 + q;          // 16B granule of this k-half

        uint32_t bf[2][4];
        const uint32_t bb = w_base + (uint32_t)(s * 1024);
#pragma unroll
        for (int ntp = 0; ntp < 2; ++ntp) {
            asm volatile(
                "ldmatrix.sync.aligned.m8n8.x4.trans.shared.b16 {%0,%1,%2,%3}, [%4];"
                : "=r"(bf[ntp][0]), "=r"(bf[ntp][1]),
                  "=r"(bf[ntp][2]), "=r"(bf[ntp][3])
                : "r"(bb + boff[ntp]));
        }

#pragma unroll
        for (int t = 0; t < MT; ++t) {
            uint32_t a0, a1, a2, a3;
            const uint32_t a_addr = in_base
                + (uint32_t)(colpart[t][kw] + kh * (NCOL * 64))
                + (uint32_t)((j ^ csel[t][kw]) << 4);
            asm volatile(
                "ldmatrix.sync.aligned.m8n8.x4.shared.b16 {%0,%1,%2,%3}, [%4];"
                : "=r"(a0), "=r"(a1), "=r"(a2), "=r"(a3) : "r"(a_addr));
#pragma unroll
            for (int nt = 0; nt < 4; ++nt) {
                const uint32_t b0 = bf[nt >> 1][(nt & 1) * 2 + 0];
                const uint32_t b1 = bf[nt >> 1][(nt & 1) * 2 + 1];
                asm volatile(
                    "mma.sync.aligned.m16n8k16.row.col.f32.f16.f16.f32 "
                    "{%0,%1,%2,%3}, {%4,%5,%6,%7}, {%8,%9}, {%0,%1,%2,%3};"
                    : "+f"(acc[t][nt][0]), "+f"(acc[t][nt][1]),
                      "+f"(acc[t][nt][2]), "+f"(acc[t][nt][3])
                    : "r"(a0), "r"(a1), "r"(a2), "r"(a3),
                      "r"(b0), "r"(b1));
            }
        }
    }

    // ---- Epilogue ----
    const int r0 = lane >> 2;
    const int n2 = (lane & 3) * 2;
    const long base_off = ((long)b * H + h0) * W;
#pragma unroll
    for (int t = 0; t < MT; ++t) {
        const int pxb = (warp * MT + t) * 16;
#pragma unroll
        for (int half = 0; half < 2; ++half) {
            const int px = pxb + r0 + half * 8;
            const int hr = px / W;
            const int wc = px - hr * W;
            const long po = (base_off + (long)hr * W + wc) * C;
#pragma unroll
            for (int nt = 0; nt < 4; ++nt) {
                const int co = g * CG + nt * 8 + n2;
                const float2 bv = *reinterpret_cast<const float2*>(&bias[co]);
                float2 o = make_float2(acc[t][nt][half * 2 + 0] + bv.x,
                                       acc[t][nt][half * 2 + 1] + bv.y);
                *reinterpret_cast<float2*>(&out[po + co]) = o;
            }
        }
    }
}

extern "C" void kernel_launch(void* const* d_in, const int* in_sizes, int n_in,
                              void* d_out, int out_size)
{
    const float* in   = (const float*)d_in[0];
    const float* wgt  = (const float*)d_in[1];
    const float* bias = (const float*)d_in[2];
    float* out = (float*)d_out;

    // Host-side attribute set: no allocation, deterministic, graph-legal.
    cudaFuncSetAttribute(groupconv_hmma,
                         cudaFuncAttributeMaxDynamicSharedMemorySize,
                         SMEM_TOTAL);

    const int grid = 8 * (H / ROWS) * B;   // 8 * 7 * 32 = 1792 blocks
    groupconv_hmma<<<grid, THREADS, SMEM_TOTAL>>>(in, wgt, bias, out);
}